// round 16
// baseline (speedup 1.0000x reference)
#include <cuda_runtime.h>
#include <cuda_bf16.h>
#include <cstdint>

#define BATCH 4
#define T 2048
#define C 1024
#define H 64
#define M_TOTAL (BATCH * T)   // 8192
#define NSPLIT 4

// Scratch (allocation-free rule: __device__ globals)
__device__ float g_opart[NSPLIT][BATCH * T * H];
__device__ float g_m[NSPLIT][BATCH * T];
__device__ float g_l[NSPLIT][BATCH * T];
__device__ __nv_bfloat16 g_wh[192 * C];        // [Wq;Wk;Wv] bf16 hi
__device__ __nv_bfloat16 g_wl[192 * C];        // bf16 lo
__device__ __nv_bfloat16 g_qh[M_TOTAL * H];    // q (scale folded) hi/lo
__device__ __nv_bfloat16 g_ql[M_TOTAL * H];
__device__ __nv_bfloat16 g_kh[M_TOTAL * H];
__device__ __nv_bfloat16 g_kl[M_TOTAL * H];
__device__ __nv_bfloat16 g_vth[H * M_TOTAL];   // V transposed [h][m]
__device__ __nv_bfloat16 g_vtl[H * M_TOTAL];

// ===========================================================================
// Helpers (portable sm_80+ tensor path)
// ===========================================================================
__device__ __forceinline__ uint32_t smem_to_u32(const void* p) {
    uint32_t a;
    asm("{ .reg .u64 t; cvta.to.shared.u64 t, %1; cvt.u32.u64 %0, t; }" : "=r"(a) : "l"(p));
    return a;
}
__device__ __forceinline__ void ldsm4(uint32_t* r, uint32_t addr) {
    asm volatile("ldmatrix.sync.aligned.m8n8.x4.shared.b16 {%0,%1,%2,%3}, [%4];"
                 : "=r"(r[0]), "=r"(r[1]), "=r"(r[2]), "=r"(r[3]) : "r"(addr));
}
__device__ __forceinline__ void mma16816(float* d, const uint32_t* a, const uint32_t* b) {
    asm volatile(
        "mma.sync.aligned.m16n8k16.row.col.f32.bf16.bf16.f32 "
        "{%0,%1,%2,%3}, {%4,%5,%6,%7}, {%8,%9}, {%0,%1,%2,%3};"
        : "+f"(d[0]), "+f"(d[1]), "+f"(d[2]), "+f"(d[3])
        : "r"(a[0]), "r"(a[1]), "r"(a[2]), "r"(a[3]), "r"(b[0]), "r"(b[1]));
}
__device__ __forceinline__ void cp16(uint32_t smem_addr, const void* gptr) {
    asm volatile("cp.async.cg.shared.global [%0], [%1], 16;" :: "r"(smem_addr), "l"(gptr));
}
__device__ __forceinline__ void cp_commit() { asm volatile("cp.async.commit_group;" ::: "memory"); }
template <int N>
__device__ __forceinline__ void cp_wait() {
    asm volatile("cp.async.wait_group %0;" :: "n"(N) : "memory");
}

__device__ __forceinline__ void split2(float a, float b, uint32_t& hi, uint32_t& lo) {
    __nv_bfloat16 ha = __float2bfloat16_rn(a);
    __nv_bfloat16 hb = __float2bfloat16_rn(b);
    float ra = a - __bfloat162float(ha);
    float rb = b - __bfloat162float(hb);
    __nv_bfloat16 la = __float2bfloat16_rn(ra);
    __nv_bfloat16 lb = __float2bfloat16_rn(rb);
    hi = (uint32_t)__bfloat16_as_ushort(ha) | ((uint32_t)__bfloat16_as_ushort(hb) << 16);
    lo = (uint32_t)__bfloat16_as_ushort(la) | ((uint32_t)__bfloat16_as_ushort(lb) << 16);
}

// ===========================================================================
// W -> bf16 hi/lo (tiny)
// ===========================================================================
__global__ __launch_bounds__(256) void wconv_kernel(
    const float* __restrict__ Wq, const float* __restrict__ Wk, const float* __restrict__ Wv)
{
    int idx = blockIdx.x * 256 + threadIdx.x;
    int r = idx >> 8;
    int c = idx & 255;
    const float* W = (r < 64) ? Wq : ((r < 128) ? Wk : Wv);
    int rr = r & 63;
    float4 w = *(const float4*)(W + (size_t)rr * C + c * 4);
    uint32_t h0, l0, h1, l1;
    split2(w.x, w.y, h0, l0);
    split2(w.z, w.w, h1, l1);
    *(uint2*)&g_wh[(size_t)r * C + c * 4] = make_uint2(h0, h1);
    *(uint2*)&g_wl[(size_t)r * C + c * 4] = make_uint2(l0, l1);
}

// ===========================================================================
// Projection via mma.sync bf16x3 with FUSED fp32->bf16x2 conversion of x.
// BM=64, BN=96 per CTA -> grid (128, 2) = 256 CTAs.
// K-chunks of 32, THREE-stage buffering (B issued 2 iters ahead, wait<1>),
// ONE __syncthreads per chunk.  8 warps = (wm 0..3) x (wn 0..1, N=48).
// Buffer hazards (mod 3): compute reads it%3; stsA writes (it+1)%3 A-region;
// issueB writes (it+2)%3 B-region -- pairwise disjoint, sync-ordered.
// Epilogue emits bf16 hi/lo: q (x0.125), k, TRANSPOSED v.
// ===========================================================================
#define PJ_AH 0        // 64 rows x 80 B
#define PJ_AL 5120
#define PJ_BH 10240    // 96 rows x 80 B
#define PJ_BL 17920
#define PJ_BUF 25600
#define PROJ_SMEM (3 * PJ_BUF)
#define NIT 32

__global__ __launch_bounds__(256) void proj_mma_kernel(const float* __restrict__ x)
{
    extern __shared__ char sm[];
    const uint32_t sb = smem_to_u32(sm);
    const int tid  = threadIdx.x;
    const int wid  = tid >> 5;
    const int lane = tid & 31;
    const int mblk   = blockIdx.x * 64;
    const int nhalf  = blockIdx.y;         // 0 or 1 -> W rows [96*nhalf, +96)
    const int wrow0  = nhalf * 96;

    const int wm = wid & 3, wn = wid >> 2;
    const int mrow = wm * 16;
    const int nloc = wn * 48;              // local n within the 96
    const int l7 = lane & 7, lb3 = (lane >> 3) & 1, lb4 = (lane >> 4) & 1;
    const int g = lane >> 2, tig = lane & 3;

    auto issueB = [&](int it) {
        const int k0 = it * 32;
        const uint32_t bo = sb + (it % 3) * PJ_BUF;
        #pragma unroll
        for (int i = 0; i < 2; i++) {
            int idx = i * 256 + tid;
            if (idx < 384) {
                int r = idx >> 2;          // 0..95 local row
                int c = idx & 3;
                cp16(bo + PJ_BH + r * 80 + c * 16, g_wh + (size_t)(wrow0 + r) * C + k0 + c * 8);
                cp16(bo + PJ_BL + r * 80 + c * 16, g_wl + (size_t)(wrow0 + r) * C + k0 + c * 8);
            }
        }
        cp_commit();
    };
    auto ldA = [&](int it, float4* areg) {
        const int k0 = it * 32;
        #pragma unroll
        for (int i = 0; i < 2; i++) {
            int idx = i * 256 + tid;
            int row = idx >> 3, c4 = idx & 7;
            areg[i] = *(const float4*)(x + (size_t)(mblk + row) * C + k0 + c4 * 4);
        }
    };
    auto stsA = [&](int it, const float4* areg) {
        char* bo = sm + (it % 3) * PJ_BUF;
        #pragma unroll
        for (int i = 0; i < 2; i++) {
            int idx = i * 256 + tid;
            int row = idx >> 3, c4 = idx & 7;
            uint32_t h0, l0, h1, l1;
            split2(areg[i].x, areg[i].y, h0, l0);
            split2(areg[i].z, areg[i].w, h1, l1);
            *(uint2*)(bo + PJ_AH + row * 80 + c4 * 8) = make_uint2(h0, h1);
            *(uint2*)(bo + PJ_AL + row * 80 + c4 * 8) = make_uint2(l0, l1);
        }
    };

    // prologue: A(0) staged, B(0) and B(1) in flight
    float4 areg[2];
    ldA(0, areg);
    stsA(0, areg);
    issueB(0);
    issueB(1);

    float acc[6][4] = {};

    for (int it = 0; it < NIT; it++) {
        if (it + 1 < NIT) ldA(it + 1, areg);

        if (it + 1 < NIT) cp_wait<1>();    // B(it) done; B(it+1) may be in flight
        else              cp_wait<0>();    // last: only B(it) outstanding
        __syncthreads();                   // B(it)+A(it) visible; prior reads done

        if (it + 2 < NIT) issueB(it + 2);

        const uint32_t bo = sb + (it % 3) * PJ_BUF;
        #pragma unroll
        for (int ks = 0; ks < 2; ks++) {
            const uint32_t aoff = (uint32_t)(mrow + lb3 * 8 + l7) * 80 + ks * 32 + lb4 * 16;
            uint32_t ah[4], al[4];
            ldsm4(ah, bo + PJ_AH + aoff);
            ldsm4(al, bo + PJ_AL + aoff);

            #pragma unroll
            for (int t = 0; t < 3; t++) {
                const uint32_t boff = (uint32_t)(nloc + t * 16 + lb4 * 8 + l7) * 80
                                    + ks * 32 + lb3 * 16;
                uint32_t bh[4], bl[4];
                ldsm4(bh, bo + PJ_BH + boff);
                ldsm4(bl, bo + PJ_BL + boff);
                #pragma unroll
                for (int s2 = 0; s2 < 2; s2++) {
                    const int nt = t * 2 + s2;
                    mma16816(acc[nt], ah, &bh[s2 * 2]);
                    mma16816(acc[nt], ah, &bl[s2 * 2]);
                    mma16816(acc[nt], al, &bh[s2 * 2]);
                }
            }
        }

        if (it + 1 < NIT) stsA(it + 1, areg);   // buffer (it+1)%3 (disjoint)
    }

    // epilogue -> bf16 hi/lo globals
    const int m1 = mblk + mrow + g;
    #pragma unroll
    for (int nt = 0; nt < 6; nt++) {
        const int col = wrow0 + nloc + nt * 8 + tig * 2;   // global col in [0,192)
        const int j   = col >> 6;
        const int hc  = col & 63;
        if (j == 0) {
            uint32_t h0, l0;
            split2(acc[nt][0] * 0.125f, acc[nt][1] * 0.125f, h0, l0);
            *(uint32_t*)&g_qh[(size_t)m1 * H + hc] = h0;
            *(uint32_t*)&g_ql[(size_t)m1 * H + hc] = l0;
            split2(acc[nt][2] * 0.125f, acc[nt][3] * 0.125f, h0, l0);
            *(uint32_t*)&g_qh[(size_t)(m1 + 8) * H + hc] = h0;
            *(uint32_t*)&g_ql[(size_t)(m1 + 8) * H + hc] = l0;
        } else if (j == 1) {
            uint32_t h0, l0;
            split2(acc[nt][0], acc[nt][1], h0, l0);
            *(uint32_t*)&g_kh[(size_t)m1 * H + hc] = h0;
            *(uint32_t*)&g_kl[(size_t)m1 * H + hc] = l0;
            split2(acc[nt][2], acc[nt][3], h0, l0);
            *(uint32_t*)&g_kh[(size_t)(m1 + 8) * H + hc] = h0;
            *(uint32_t*)&g_kl[(size_t)(m1 + 8) * H + hc] = l0;
        } else {
            #pragma unroll
            for (int k = 0; k < 4; k++) {
                int r  = m1 + (k >> 1) * 8;
                int cc = hc + (k & 1);
                float v = acc[nt][k];
                __nv_bfloat16 hi = __float2bfloat16_rn(v);
                __nv_bfloat16 lo = __float2bfloat16_rn(v - __bfloat162float(hi));
                g_vth[(size_t)cc * M_TOTAL + r] = hi;
                g_vtl[(size_t)cc * M_TOTAL + r] = lo;
            }
        }
    }
}

// ===========================================================================
// Flash attention on mma.sync, bf16x3.  BM=64, BN=64, 8 warps.
// Split-KV over blockIdx.z (NSPLIT=4), heavy-first q-tile order.
// ===========================================================================
#define STR 144                  // SMEM row stride bytes (64 bf16 + 16B pad)
#define A_QH 0
#define A_QL 9216
#define A_KH 18432
#define A_KL 27648
#define A_VH 36864
#define A_VL 46080
#define A_PH 55296
#define A_PL 64512
#define A_MAX 73728              // float[2][64]
#define A_SUM 74240              // float[2][64]
#define ATTN_SMEM 74752

__global__ __launch_bounds__(256) void attn_mma_kernel()
{
    extern __shared__ char sm[];
    const uint32_t sb = smem_to_u32(sm);
    const int tid  = threadIdx.x;
    const int wid  = tid >> 5;
    const int lane = tid & 31;
    const int wm = wid & 3, wn = wid >> 2;
    const int g = lane >> 2, tig = lane & 3;
    const int l7 = lane & 7, lb3 = (lane >> 3) & 1, lb4 = (lane >> 4) & 1;

    const int b  = blockIdx.y;
    const int sp = blockIdx.z;
    const int qt = (T / 64 - 1) - blockIdx.x;   // heavy-first
    const int q0 = qt * 64;
    const int bT = b * T;

    const int ntiles = qt + 1;
    const int kt_beg = (sp * ntiles) / NSPLIT;
    const int kt_end = ((sp + 1) * ntiles) / NSPLIT;

    const int rr0  = 16 * wm + g;
    const int orow = bT + q0 + rr0;

    if (kt_beg >= kt_end) {   // empty split: neutral partials
        #pragma unroll
        for (int nt = 0; nt < 4; nt++) {
            int c = 32 * wn + nt * 8 + tig * 2;
            *(float2*)&g_opart[sp][(size_t)orow * H + c]       = make_float2(0.f, 0.f);
            *(float2*)&g_opart[sp][(size_t)(orow + 8) * H + c] = make_float2(0.f, 0.f);
        }
        if (wn == 0 && tig == 0) {
            g_m[sp][orow] = -1e30f; g_m[sp][orow + 8] = -1e30f;
            g_l[sp][orow] = 0.f;    g_l[sp][orow + 8] = 0.f;
        }
        return;
    }

    auto loadK = [&](int kt) {
        int k0 = kt * 64;
        #pragma unroll
        for (int i = 0; i < 2; i++) {
            int idx = i * 256 + tid, r = idx >> 3, c = idx & 7;
            cp16(sb + A_KH + r * STR + c * 16, g_kh + (size_t)(bT + k0 + r) * H + c * 8);
            cp16(sb + A_KL + r * STR + c * 16, g_kl + (size_t)(bT + k0 + r) * H + c * 8);
        }
        cp_commit();
    };
    auto loadV = [&](int kt) {
        int k0 = kt * 64;
        #pragma unroll
        for (int i = 0; i < 2; i++) {
            int idx = i * 256 + tid, r = idx >> 3, c = idx & 7;   // r = h row
            cp16(sb + A_VH + r * STR + c * 16, g_vth + (size_t)r * M_TOTAL + bT + k0 + c * 8);
            cp16(sb + A_VL + r * STR + c * 16, g_vtl + (size_t)r * M_TOTAL + bT + k0 + c * 8);
        }
        cp_commit();
    };

    // prologue: {Q + K(kt_beg)} group, then {V(kt_beg)} group
    #pragma unroll
    for (int i = 0; i < 2; i++) {
        int idx = i * 256 + tid, r = idx >> 3, c = idx & 7;
        cp16(sb + A_QH + r * STR + c * 16, g_qh + (size_t)(bT + q0 + r) * H + c * 8);
        cp16(sb + A_QL + r * STR + c * 16, g_ql + (size_t)(bT + q0 + r) * H + c * 8);
    }
    loadK(kt_beg);
    loadV(kt_beg);

    float O[4][4] = {};
    float run_m[2] = {-1e30f, -1e30f};
    float run_l[2] = {0.f, 0.f};
    float* smax = (float*)(sm + A_MAX);
    float* ssum = (float*)(sm + A_SUM);

    for (int kt = kt_beg; kt < kt_end; kt++) {
        cp_wait<1>();            // Q+K of this tile arrived
        __syncthreads();         // S0

        // ---- S = Q K^T (bf16x3)
        float S[4][4] = {};
        #pragma unroll
        for (int ks = 0; ks < 4; ks++) {
            uint32_t ah[4], al[4];
            uint32_t aoff = (uint32_t)(16 * wm + lb3 * 8 + l7) * STR + ks * 32 + lb4 * 16;
            ldsm4(ah, sb + A_QH + aoff);
            ldsm4(al, sb + A_QL + aoff);
            #pragma unroll
            for (int t = 0; t < 2; t++) {
                uint32_t bh[4], bl[4];
                uint32_t boff = (uint32_t)(32 * wn + t * 16 + lb4 * 8 + l7) * STR + ks * 32 + lb3 * 16;
                ldsm4(bh, sb + A_KH + boff);
                ldsm4(bl, sb + A_KL + boff);
                #pragma unroll
                for (int s2 = 0; s2 < 2; s2++) {
                    const int nt = t * 2 + s2;
                    mma16816(S[nt], ah, &bh[s2 * 2]);
                    mma16816(S[nt], ah, &bl[s2 * 2]);
                    mma16816(S[nt], al, &bh[s2 * 2]);
                }
            }
        }

        const int k0 = kt * 64;
        if (kt == qt) {   // diagonal mask
            #pragma unroll
            for (int nt = 0; nt < 4; nt++)
                #pragma unroll
                for (int k = 0; k < 4; k++) {
                    int row = q0 + rr0 + (k >> 1) * 8;
                    int col = k0 + 32 * wn + nt * 8 + tig * 2 + (k & 1);
                    if (col > row) S[nt][k] = -1e30f;
                }
        }

        // ---- row max (in-warp + cross-warp via SMEM)
        float pm0 = -1e30f, pm1 = -1e30f;
        #pragma unroll
        for (int nt = 0; nt < 4; nt++) {
            pm0 = fmaxf(pm0, fmaxf(S[nt][0], S[nt][1]));
            pm1 = fmaxf(pm1, fmaxf(S[nt][2], S[nt][3]));
        }
        pm0 = fmaxf(pm0, __shfl_xor_sync(~0u, pm0, 1));
        pm0 = fmaxf(pm0, __shfl_xor_sync(~0u, pm0, 2));
        pm1 = fmaxf(pm1, __shfl_xor_sync(~0u, pm1, 1));
        pm1 = fmaxf(pm1, __shfl_xor_sync(~0u, pm1, 2));
        if (tig == 0) { smax[wn * 64 + rr0] = pm0; smax[wn * 64 + rr0 + 8] = pm1; }
        __syncthreads();         // S1 (also: all QK^T reads of K done)

        if (kt + 1 < kt_end) loadK(kt + 1);   // overlap next-K with softmax+PV

        float nm0 = fmaxf(run_m[0], fmaxf(smax[rr0],     smax[64 + rr0]));
        float nm1 = fmaxf(run_m[1], fmaxf(smax[rr0 + 8], smax[64 + rr0 + 8]));
        float al0 = __expf(run_m[0] - nm0);
        float al1 = __expf(run_m[1] - nm1);

        float rs0 = 0.f, rs1 = 0.f;
        #pragma unroll
        for (int nt = 0; nt < 4; nt++) {
            float p0 = __expf(S[nt][0] - nm0), p1 = __expf(S[nt][1] - nm0);
            float p2 = __expf(S[nt][2] - nm1), p3 = __expf(S[nt][3] - nm1);
            rs0 += p0 + p1; rs1 += p2 + p3;
            uint32_t h0, l0, h1, l1;
            split2(p0, p1, h0, l0);
            split2(p2, p3, h1, l1);
            uint32_t cb = (uint32_t)(32 * wn + nt * 8 + tig * 2) * 2;
            *(uint32_t*)(sm + A_PH + rr0 * STR + cb) = h0;
            *(uint32_t*)(sm + A_PL + rr0 * STR + cb) = l0;
            *(uint32_t*)(sm + A_PH + (rr0 + 8) * STR + cb) = h1;
            *(uint32_t*)(sm + A_PL + (rr0 + 8) * STR + cb) = l1;
        }
        rs0 += __shfl_xor_sync(~0u, rs0, 1); rs0 += __shfl_xor_sync(~0u, rs0, 2);
        rs1 += __shfl_xor_sync(~0u, rs1, 1); rs1 += __shfl_xor_sync(~0u, rs1, 2);
        if (tig == 0) { ssum[wn * 64 + rr0] = rs0; ssum[wn * 64 + rr0 + 8] = rs1; }

        if (kt + 1 < kt_end) cp_wait<1>();    // V of this tile arrived (next-K in flight)
        else                 cp_wait<0>();
        __syncthreads();         // S2 (P, sums, V visible)

        run_l[0] = run_l[0] * al0 + ssum[rr0]     + ssum[64 + rr0];
        run_l[1] = run_l[1] * al1 + ssum[rr0 + 8] + ssum[64 + rr0 + 8];
        run_m[0] = nm0; run_m[1] = nm1;
        #pragma unroll
        for (int nt = 0; nt < 4; nt++) {
            O[nt][0] *= al0; O[nt][1] *= al0; O[nt][2] *= al1; O[nt][3] *= al1;
        }

        // ---- O += P V (bf16x3)
        #pragma unroll
        for (int kk = 0; kk < 4; kk++) {
            uint32_t ph[4], pl[4];
            uint32_t aoff = (uint32_t)(16 * wm + lb3 * 8 + l7) * STR + kk * 32 + lb4 * 16;
            ldsm4(ph, sb + A_PH + aoff);
            ldsm4(pl, sb + A_PL + aoff);
            #pragma unroll
            for (int t = 0; t < 2; t++) {
                uint32_t vh[4], vl[4];
                uint32_t boff = (uint32_t)(32 * wn + t * 16 + lb4 * 8 + l7) * STR + kk * 32 + lb3 * 16;
                ldsm4(vh, sb + A_VH + boff);
                ldsm4(vl, sb + A_VL + boff);
                #pragma unroll
                for (int s2 = 0; s2 < 2; s2++) {
                    const int nt = t * 2 + s2;
                    mma16816(O[nt], ph, &vh[s2 * 2]);
                    mma16816(O[nt], ph, &vl[s2 * 2]);
                    mma16816(O[nt], pl, &vh[s2 * 2]);
                }
            }
        }
        __syncthreads();         // S3 (V reads done -> buffer reusable)
        if (kt + 1 < kt_end) loadV(kt + 1);
    }

    // epilogue: unnormalized O + (m, l)
    #pragma unroll
    for (int nt = 0; nt < 4; nt++) {
        int c = 32 * wn + nt * 8 + tig * 2;
        *(float2*)&g_opart[sp][(size_t)orow * H + c]       = make_float2(O[nt][0], O[nt][1]);
        *(float2*)&g_opart[sp][(size_t)(orow + 8) * H + c] = make_float2(O[nt][2], O[nt][3]);
    }
    if (wn == 0 && tig == 0) {
        g_m[sp][orow] = run_m[0]; g_m[sp][orow + 8] = run_m[1];
        g_l[sp][orow] = run_l[0]; g_l[sp][orow + 8] = run_l[1];
    }
}

// ===========================================================================
// Combine the NSPLIT partials
// ===========================================================================
__global__ __launch_bounds__(256) void combine_kernel(float* __restrict__ out)
{
    int idx = blockIdx.x * 256 + threadIdx.x;
    int row = idx >> 4;
    int c4  = (idx & 15) * 4;

    float mv[NSPLIT], lv[NSPLIT];
    float M = -1e30f;
    #pragma unroll
    for (int s = 0; s < NSPLIT; s++) {
        mv[s] = g_m[s][row];
        lv[s] = g_l[s][row];
        M = fmaxf(M, mv[s]);
    }
    float w[NSPLIT], denom = 0.f;
    #pragma unroll
    for (int s = 0; s < NSPLIT; s++) {
        w[s] = __expf(mv[s] - M);
        denom += w[s] * lv[s];
    }
    float inv = 1.0f / denom;

    float4 r = make_float4(0.f, 0.f, 0.f, 0.f);
    #pragma unroll
    for (int s = 0; s < NSPLIT; s++) {
        float4 o = *(const float4*)&g_opart[s][(size_t)row * H + c4];
        r.x += w[s] * o.x; r.y += w[s] * o.y; r.z += w[s] * o.z; r.w += w[s] * o.w;
    }
    r.x *= inv; r.y *= inv; r.z *= inv; r.w *= inv;
    *(float4*)&out[(size_t)row * H + c4] = r;
}

// ===========================================================================
extern "C" void kernel_launch(void* const* d_in, const int* in_sizes, int n_in,
                              void* d_out, int out_size)
{
    const float* x  = (const float*)d_in[0];
    const float* Wq = (const float*)d_in[1];
    const float* Wk = (const float*)d_in[2];
    const float* Wv = (const float*)d_in[3];
    float* out = (float*)d_out;

    cudaFuncSetAttribute(proj_mma_kernel,
                         cudaFuncAttributeMaxDynamicSharedMemorySize, PROJ_SMEM);
    cudaFuncSetAttribute(attn_mma_kernel,
                         cudaFuncAttributeMaxDynamicSharedMemorySize, ATTN_SMEM);

    wconv_kernel<<<192, 256>>>(Wq, Wk, Wv);
    proj_mma_kernel<<<dim3(M_TOTAL / 64, 2), 256, PROJ_SMEM>>>(x);
    attn_mma_kernel<<<dim3(T / 64, BATCH, NSPLIT), 256, ATTN_SMEM>>>();
    combine_kernel<<<(M_TOTAL * (H / 4)) / 256, 256>>>(out);
}

// round 17
// speedup vs baseline: 1.0072x; 1.0072x over previous
#include <cuda_runtime.h>
#include <cuda_bf16.h>
#include <cstdint>

#define BATCH 4
#define T 2048
#define C 1024
#define H 64
#define M_TOTAL (BATCH * T)   // 8192
#define NSPLIT 4

// Scratch (allocation-free rule: __device__ globals)
__device__ float g_opart[NSPLIT][BATCH * T * H];
__device__ float g_m[NSPLIT][BATCH * T];
__device__ float g_l[NSPLIT][BATCH * T];
__device__ __nv_bfloat16 g_wh[192 * C];        // [Wq;Wk;Wv] bf16 hi
__device__ __nv_bfloat16 g_wl[192 * C];        // bf16 lo
__device__ __nv_bfloat16 g_qh[M_TOTAL * H];    // q (scale folded) hi/lo
__device__ __nv_bfloat16 g_ql[M_TOTAL * H];
__device__ __nv_bfloat16 g_kh[M_TOTAL * H];
__device__ __nv_bfloat16 g_kl[M_TOTAL * H];
__device__ __nv_bfloat16 g_vth[H * M_TOTAL];   // V transposed [h][m]
__device__ __nv_bfloat16 g_vtl[H * M_TOTAL];

// ===========================================================================
// Helpers (portable sm_80+ tensor path)
// ===========================================================================
__device__ __forceinline__ uint32_t smem_to_u32(const void* p) {
    uint32_t a;
    asm("{ .reg .u64 t; cvta.to.shared.u64 t, %1; cvt.u32.u64 %0, t; }" : "=r"(a) : "l"(p));
    return a;
}
__device__ __forceinline__ void ldsm4(uint32_t* r, uint32_t addr) {
    asm volatile("ldmatrix.sync.aligned.m8n8.x4.shared.b16 {%0,%1,%2,%3}, [%4];"
                 : "=r"(r[0]), "=r"(r[1]), "=r"(r[2]), "=r"(r[3]) : "r"(addr));
}
__device__ __forceinline__ void mma16816(float* d, const uint32_t* a, const uint32_t* b) {
    asm volatile(
        "mma.sync.aligned.m16n8k16.row.col.f32.bf16.bf16.f32 "
        "{%0,%1,%2,%3}, {%4,%5,%6,%7}, {%8,%9}, {%0,%1,%2,%3};"
        : "+f"(d[0]), "+f"(d[1]), "+f"(d[2]), "+f"(d[3])
        : "r"(a[0]), "r"(a[1]), "r"(a[2]), "r"(a[3]), "r"(b[0]), "r"(b[1]));
}
__device__ __forceinline__ void cp16(uint32_t smem_addr, const void* gptr) {
    asm volatile("cp.async.cg.shared.global [%0], [%1], 16;" :: "r"(smem_addr), "l"(gptr));
}
__device__ __forceinline__ void cp_commit() { asm volatile("cp.async.commit_group;" ::: "memory"); }
template <int N>
__device__ __forceinline__ void cp_wait() {
    asm volatile("cp.async.wait_group %0;" :: "n"(N) : "memory");
}

__device__ __forceinline__ void split2(float a, float b, uint32_t& hi, uint32_t& lo) {
    __nv_bfloat16 ha = __float2bfloat16_rn(a);
    __nv_bfloat16 hb = __float2bfloat16_rn(b);
    float ra = a - __bfloat162float(ha);
    float rb = b - __bfloat162float(hb);
    __nv_bfloat16 la = __float2bfloat16_rn(ra);
    __nv_bfloat16 lb = __float2bfloat16_rn(rb);
    hi = (uint32_t)__bfloat16_as_ushort(ha) | ((uint32_t)__bfloat16_as_ushort(hb) << 16);
    lo = (uint32_t)__bfloat16_as_ushort(la) | ((uint32_t)__bfloat16_as_ushort(lb) << 16);
}

// ===========================================================================
// W -> bf16 hi/lo (tiny)
// ===========================================================================
__global__ __launch_bounds__(256) void wconv_kernel(
    const float* __restrict__ Wq, const float* __restrict__ Wk, const float* __restrict__ Wv)
{
    int idx = blockIdx.x * 256 + threadIdx.x;
    int r = idx >> 8;
    int c = idx & 255;
    const float* W = (r < 64) ? Wq : ((r < 128) ? Wk : Wv);
    int rr = r & 63;
    float4 w = *(const float4*)(W + (size_t)rr * C + c * 4);
    uint32_t h0, l0, h1, l1;
    split2(w.x, w.y, h0, l0);
    split2(w.z, w.w, h1, l1);
    *(uint2*)&g_wh[(size_t)r * C + c * 4] = make_uint2(h0, h1);
    *(uint2*)&g_wl[(size_t)r * C + c * 4] = make_uint2(l0, l1);
}

// ===========================================================================
// Projection via mma.sync bf16x3 with FUSED fp32->bf16x2 conversion of x.
// BM=64, BN=96 per CTA -> grid (128, 2) = 256 CTAs.
// BK=64: 16 K-chunks, double-buffered, ONE __syncthreads per chunk
// (72 MMAs per sync -- 2x amortization vs BK=32).
// Row stride 144 B (128 data + 16 pad, conflict-free ldmatrix).
// 8 warps = (wm 0..3 m-tiles) x (wn 0..1, N=48 each).
// Epilogue emits bf16 hi/lo: q (x0.125), k, TRANSPOSED v.
// ===========================================================================
#define PJ_AH 0        // 64 rows x 144 B = 9216
#define PJ_AL 9216
#define PJ_BH 18432    // 96 rows x 144 B = 13824
#define PJ_BL 32256
#define PJ_BUF 46080
#define PROJ_SMEM (2 * PJ_BUF)
#define NIT 16

__global__ __launch_bounds__(256) void proj_mma_kernel(const float* __restrict__ x)
{
    extern __shared__ char sm[];
    const uint32_t sb = smem_to_u32(sm);
    const int tid  = threadIdx.x;
    const int wid  = tid >> 5;
    const int lane = tid & 31;
    const int mblk   = blockIdx.x * 64;
    const int nhalf  = blockIdx.y;         // 0 or 1 -> W rows [96*nhalf, +96)
    const int wrow0  = nhalf * 96;

    const int wm = wid & 3, wn = wid >> 2;
    const int mrow = wm * 16;
    const int nloc = wn * 48;              // local n within the 96
    const int l7 = lane & 7, lb3 = (lane >> 3) & 1, lb4 = (lane >> 4) & 1;
    const int g = lane >> 2, tig = lane & 3;

    auto issueB = [&](int it) {
        const int k0 = it * 64;
        const uint32_t bo = sb + (it & 1) * PJ_BUF;
        #pragma unroll
        for (int i = 0; i < 3; i++) {
            int idx = i * 256 + tid;       // 0..767
            int r = idx >> 3;              // 0..95 local row
            int c = idx & 7;               // 8 x 16B = 128B row
            cp16(bo + PJ_BH + r * 144 + c * 16, g_wh + (size_t)(wrow0 + r) * C + k0 + c * 8);
            cp16(bo + PJ_BL + r * 144 + c * 16, g_wl + (size_t)(wrow0 + r) * C + k0 + c * 8);
        }
        cp_commit();
    };
    auto ldA = [&](int it, float4* areg) {
        const int k0 = it * 64;
        #pragma unroll
        for (int i = 0; i < 4; i++) {
            int idx = i * 256 + tid;
            int row = idx >> 4, c4 = idx & 15;
            areg[i] = *(const float4*)(x + (size_t)(mblk + row) * C + k0 + c4 * 4);
        }
    };
    auto stsA = [&](int it, const float4* areg) {
        char* bo = sm + (it & 1) * PJ_BUF;
        #pragma unroll
        for (int i = 0; i < 4; i++) {
            int idx = i * 256 + tid;
            int row = idx >> 4, c4 = idx & 15;
            uint32_t h0, l0, h1, l1;
            split2(areg[i].x, areg[i].y, h0, l0);
            split2(areg[i].z, areg[i].w, h1, l1);
            *(uint2*)(bo + PJ_AH + row * 144 + c4 * 8) = make_uint2(h0, h1);
            *(uint2*)(bo + PJ_AL + row * 144 + c4 * 8) = make_uint2(l0, l1);
        }
    };

    // prologue
    float4 areg[4];
    ldA(0, areg);
    stsA(0, areg);
    issueB(0);

    float acc[6][4] = {};

    for (int it = 0; it < NIT; it++) {
        if (it + 1 < NIT) ldA(it + 1, areg);

        cp_wait<0>();
        __syncthreads();            // B(it) + A(it) visible; all prior reads done

        if (it + 1 < NIT) issueB(it + 1);

        const uint32_t bo = sb + (it & 1) * PJ_BUF;
        #pragma unroll
        for (int ks = 0; ks < 4; ks++) {
            const uint32_t aoff = (uint32_t)(mrow + lb3 * 8 + l7) * 144 + ks * 32 + lb4 * 16;
            uint32_t ah[4], al[4];
            ldsm4(ah, bo + PJ_AH + aoff);
            ldsm4(al, bo + PJ_AL + aoff);

            #pragma unroll
            for (int t = 0; t < 3; t++) {
                const uint32_t boff = (uint32_t)(nloc + t * 16 + lb4 * 8 + l7) * 144
                                    + ks * 32 + lb3 * 16;
                uint32_t bh[4], bl[4];
                ldsm4(bh, bo + PJ_BH + boff);
                ldsm4(bl, bo + PJ_BL + boff);
                #pragma unroll
                for (int s2 = 0; s2 < 2; s2++) {
                    const int nt = t * 2 + s2;
                    mma16816(acc[nt], ah, &bh[s2 * 2]);
                    mma16816(acc[nt], ah, &bl[s2 * 2]);
                    mma16816(acc[nt], al, &bh[s2 * 2]);
                }
            }
        }

        if (it + 1 < NIT) stsA(it + 1, areg);   // into buffer (it+1)&1 (disjoint)
    }

    // epilogue -> bf16 hi/lo globals
    const int m1 = mblk + mrow + g;
    #pragma unroll
    for (int nt = 0; nt < 6; nt++) {
        const int col = wrow0 + nloc + nt * 8 + tig * 2;   // global col in [0,192)
        const int j   = col >> 6;
        const int hc  = col & 63;
        if (j == 0) {
            uint32_t h0, l0;
            split2(acc[nt][0] * 0.125f, acc[nt][1] * 0.125f, h0, l0);
            *(uint32_t*)&g_qh[(size_t)m1 * H + hc] = h0;
            *(uint32_t*)&g_ql[(size_t)m1 * H + hc] = l0;
            split2(acc[nt][2] * 0.125f, acc[nt][3] * 0.125f, h0, l0);
            *(uint32_t*)&g_qh[(size_t)(m1 + 8) * H + hc] = h0;
            *(uint32_t*)&g_ql[(size_t)(m1 + 8) * H + hc] = l0;
        } else if (j == 1) {
            uint32_t h0, l0;
            split2(acc[nt][0], acc[nt][1], h0, l0);
            *(uint32_t*)&g_kh[(size_t)m1 * H + hc] = h0;
            *(uint32_t*)&g_kl[(size_t)m1 * H + hc] = l0;
            split2(acc[nt][2], acc[nt][3], h0, l0);
            *(uint32_t*)&g_kh[(size_t)(m1 + 8) * H + hc] = h0;
            *(uint32_t*)&g_kl[(size_t)(m1 + 8) * H + hc] = l0;
        } else {
            #pragma unroll
            for (int k = 0; k < 4; k++) {
                int r  = m1 + (k >> 1) * 8;
                int cc = hc + (k & 1);
                float v = acc[nt][k];
                __nv_bfloat16 hi = __float2bfloat16_rn(v);
                __nv_bfloat16 lo = __float2bfloat16_rn(v - __bfloat162float(hi));
                g_vth[(size_t)cc * M_TOTAL + r] = hi;
                g_vtl[(size_t)cc * M_TOTAL + r] = lo;
            }
        }
    }
}

// ===========================================================================
// Flash attention on mma.sync, bf16x3.  BM=64, BN=64, 8 warps.
// Split-KV over blockIdx.z (NSPLIT=4), heavy-first q-tile order.
// ===========================================================================
#define STR 144                  // SMEM row stride bytes (64 bf16 + 16B pad)
#define A_QH 0
#define A_QL 9216
#define A_KH 18432
#define A_KL 27648
#define A_VH 36864
#define A_VL 46080
#define A_PH 55296
#define A_PL 64512
#define A_MAX 73728              // float[2][64]
#define A_SUM 74240              // float[2][64]
#define ATTN_SMEM 74752

__global__ __launch_bounds__(256) void attn_mma_kernel()
{
    extern __shared__ char sm[];
    const uint32_t sb = smem_to_u32(sm);
    const int tid  = threadIdx.x;
    const int wid  = tid >> 5;
    const int lane = tid & 31;
    const int wm = wid & 3, wn = wid >> 2;
    const int g = lane >> 2, tig = lane & 3;
    const int l7 = lane & 7, lb3 = (lane >> 3) & 1, lb4 = (lane >> 4) & 1;

    const int b  = blockIdx.y;
    const int sp = blockIdx.z;
    const int qt = (T / 64 - 1) - blockIdx.x;   // heavy-first
    const int q0 = qt * 64;
    const int bT = b * T;

    const int ntiles = qt + 1;
    const int kt_beg = (sp * ntiles) / NSPLIT;
    const int kt_end = ((sp + 1) * ntiles) / NSPLIT;

    const int rr0  = 16 * wm + g;
    const int orow = bT + q0 + rr0;

    if (kt_beg >= kt_end) {   // empty split: neutral partials
        #pragma unroll
        for (int nt = 0; nt < 4; nt++) {
            int c = 32 * wn + nt * 8 + tig * 2;
            *(float2*)&g_opart[sp][(size_t)orow * H + c]       = make_float2(0.f, 0.f);
            *(float2*)&g_opart[sp][(size_t)(orow + 8) * H + c] = make_float2(0.f, 0.f);
        }
        if (wn == 0 && tig == 0) {
            g_m[sp][orow] = -1e30f; g_m[sp][orow + 8] = -1e30f;
            g_l[sp][orow] = 0.f;    g_l[sp][orow + 8] = 0.f;
        }
        return;
    }

    auto loadK = [&](int kt) {
        int k0 = kt * 64;
        #pragma unroll
        for (int i = 0; i < 2; i++) {
            int idx = i * 256 + tid, r = idx >> 3, c = idx & 7;
            cp16(sb + A_KH + r * STR + c * 16, g_kh + (size_t)(bT + k0 + r) * H + c * 8);
            cp16(sb + A_KL + r * STR + c * 16, g_kl + (size_t)(bT + k0 + r) * H + c * 8);
        }
        cp_commit();
    };
    auto loadV = [&](int kt) {
        int k0 = kt * 64;
        #pragma unroll
        for (int i = 0; i < 2; i++) {
            int idx = i * 256 + tid, r = idx >> 3, c = idx & 7;   // r = h row
            cp16(sb + A_VH + r * STR + c * 16, g_vth + (size_t)r * M_TOTAL + bT + k0 + c * 8);
            cp16(sb + A_VL + r * STR + c * 16, g_vtl + (size_t)r * M_TOTAL + bT + k0 + c * 8);
        }
        cp_commit();
    };

    // prologue: {Q + K(kt_beg)} group, then {V(kt_beg)} group
    #pragma unroll
    for (int i = 0; i < 2; i++) {
        int idx = i * 256 + tid, r = idx >> 3, c = idx & 7;
        cp16(sb + A_QH + r * STR + c * 16, g_qh + (size_t)(bT + q0 + r) * H + c * 8);
        cp16(sb + A_QL + r * STR + c * 16, g_ql + (size_t)(bT + q0 + r) * H + c * 8);
    }
    loadK(kt_beg);
    loadV(kt_beg);

    float O[4][4] = {};
    float run_m[2] = {-1e30f, -1e30f};
    float run_l[2] = {0.f, 0.f};
    float* smax = (float*)(sm + A_MAX);
    float* ssum = (float*)(sm + A_SUM);

    for (int kt = kt_beg; kt < kt_end; kt++) {
        cp_wait<1>();            // Q+K of this tile arrived
        __syncthreads();         // S0

        // ---- S = Q K^T (bf16x3)
        float S[4][4] = {};
        #pragma unroll
        for (int ks = 0; ks < 4; ks++) {
            uint32_t ah[4], al[4];
            uint32_t aoff = (uint32_t)(16 * wm + lb3 * 8 + l7) * STR + ks * 32 + lb4 * 16;
            ldsm4(ah, sb + A_QH + aoff);
            ldsm4(al, sb + A_QL + aoff);
            #pragma unroll
            for (int t = 0; t < 2; t++) {
                uint32_t bh[4], bl[4];
                uint32_t boff = (uint32_t)(32 * wn + t * 16 + lb4 * 8 + l7) * STR + ks * 32 + lb3 * 16;
                ldsm4(bh, sb + A_KH + boff);
                ldsm4(bl, sb + A_KL + boff);
                #pragma unroll
                for (int s2 = 0; s2 < 2; s2++) {
                    const int nt = t * 2 + s2;
                    mma16816(S[nt], ah, &bh[s2 * 2]);
                    mma16816(S[nt], ah, &bl[s2 * 2]);
                    mma16816(S[nt], al, &bh[s2 * 2]);
                }
            }
        }

        const int k0 = kt * 64;
        if (kt == qt) {   // diagonal mask
            #pragma unroll
            for (int nt = 0; nt < 4; nt++)
                #pragma unroll
                for (int k = 0; k < 4; k++) {
                    int row = q0 + rr0 + (k >> 1) * 8;
                    int col = k0 + 32 * wn + nt * 8 + tig * 2 + (k & 1);
                    if (col > row) S[nt][k] = -1e30f;
                }
        }

        // ---- row max (in-warp + cross-warp via SMEM)
        float pm0 = -1e30f, pm1 = -1e30f;
        #pragma unroll
        for (int nt = 0; nt < 4; nt++) {
            pm0 = fmaxf(pm0, fmaxf(S[nt][0], S[nt][1]));
            pm1 = fmaxf(pm1, fmaxf(S[nt][2], S[nt][3]));
        }
        pm0 = fmaxf(pm0, __shfl_xor_sync(~0u, pm0, 1));
        pm0 = fmaxf(pm0, __shfl_xor_sync(~0u, pm0, 2));
        pm1 = fmaxf(pm1, __shfl_xor_sync(~0u, pm1, 1));
        pm1 = fmaxf(pm1, __shfl_xor_sync(~0u, pm1, 2));
        if (tig == 0) { smax[wn * 64 + rr0] = pm0; smax[wn * 64 + rr0 + 8] = pm1; }
        __syncthreads();         // S1 (also: all QK^T reads of K done)

        if (kt + 1 < kt_end) loadK(kt + 1);   // overlap next-K with softmax+PV

        float nm0 = fmaxf(run_m[0], fmaxf(smax[rr0],     smax[64 + rr0]));
        float nm1 = fmaxf(run_m[1], fmaxf(smax[rr0 + 8], smax[64 + rr0 + 8]));
        float al0 = __expf(run_m[0] - nm0);
        float al1 = __expf(run_m[1] - nm1);

        float rs0 = 0.f, rs1 = 0.f;
        #pragma unroll
        for (int nt = 0; nt < 4; nt++) {
            float p0 = __expf(S[nt][0] - nm0), p1 = __expf(S[nt][1] - nm0);
            float p2 = __expf(S[nt][2] - nm1), p3 = __expf(S[nt][3] - nm1);
            rs0 += p0 + p1; rs1 += p2 + p3;
            uint32_t h0, l0, h1, l1;
            split2(p0, p1, h0, l0);
            split2(p2, p3, h1, l1);
            uint32_t cb = (uint32_t)(32 * wn + nt * 8 + tig * 2) * 2;
            *(uint32_t*)(sm + A_PH + rr0 * STR + cb) = h0;
            *(uint32_t*)(sm + A_PL + rr0 * STR + cb) = l0;
            *(uint32_t*)(sm + A_PH + (rr0 + 8) * STR + cb) = h1;
            *(uint32_t*)(sm + A_PL + (rr0 + 8) * STR + cb) = l1;
        }
        rs0 += __shfl_xor_sync(~0u, rs0, 1); rs0 += __shfl_xor_sync(~0u, rs0, 2);
        rs1 += __shfl_xor_sync(~0u, rs1, 1); rs1 += __shfl_xor_sync(~0u, rs1, 2);
        if (tig == 0) { ssum[wn * 64 + rr0] = rs0; ssum[wn * 64 + rr0 + 8] = rs1; }

        if (kt + 1 < kt_end) cp_wait<1>();    // V of this tile arrived (next-K in flight)
        else                 cp_wait<0>();
        __syncthreads();         // S2 (P, sums, V visible)

        run_l[0] = run_l[0] * al0 + ssum[rr0]     + ssum[64 + rr0];
        run_l[1] = run_l[1] * al1 + ssum[rr0 + 8] + ssum[64 + rr0 + 8];
        run_m[0] = nm0; run_m[1] = nm1;
        #pragma unroll
        for (int nt = 0; nt < 4; nt++) {
            O[nt][0] *= al0; O[nt][1] *= al0; O[nt][2] *= al1; O[nt][3] *= al1;
        }

        // ---- O += P V (bf16x3)
        #pragma unroll
        for (int kk = 0; kk < 4; kk++) {
            uint32_t ph[4], pl[4];
            uint32_t aoff = (uint32_t)(16 * wm + lb3 * 8 + l7) * STR + kk * 32 + lb4 * 16;
            ldsm4(ph, sb + A_PH + aoff);
            ldsm4(pl, sb + A_PL + aoff);
            #pragma unroll
            for (int t = 0; t < 2; t++) {
                uint32_t vh[4], vl[4];
                uint32_t boff = (uint32_t)(32 * wn + t * 16 + lb4 * 8 + l7) * STR + kk * 32 + lb3 * 16;
                ldsm4(vh, sb + A_VH + boff);
                ldsm4(vl, sb + A_VL + boff);
                #pragma unroll
                for (int s2 = 0; s2 < 2; s2++) {
                    const int nt = t * 2 + s2;
                    mma16816(O[nt], ph, &vh[s2 * 2]);
                    mma16816(O[nt], ph, &vl[s2 * 2]);
                    mma16816(O[nt], pl, &vh[s2 * 2]);
                }
            }
        }
        __syncthreads();         // S3 (V reads done -> buffer reusable)
        if (kt + 1 < kt_end) loadV(kt + 1);
    }

    // epilogue: unnormalized O + (m, l)
    #pragma unroll
    for (int nt = 0; nt < 4; nt++) {
        int c = 32 * wn + nt * 8 + tig * 2;
        *(float2*)&g_opart[sp][(size_t)orow * H + c]       = make_float2(O[nt][0], O[nt][1]);
        *(float2*)&g_opart[sp][(size_t)(orow + 8) * H + c] = make_float2(O[nt][2], O[nt][3]);
    }
    if (wn == 0 && tig == 0) {
        g_m[sp][orow] = run_m[0]; g_m[sp][orow + 8] = run_m[1];
        g_l[sp][orow] = run_l[0]; g_l[sp][orow + 8] = run_l[1];
    }
}

// ===========================================================================
// Combine the NSPLIT partials
// ===========================================================================
__global__ __launch_bounds__(256) void combine_kernel(float* __restrict__ out)
{
    int idx = blockIdx.x * 256 + threadIdx.x;
    int row = idx >> 4;
    int c4  = (idx & 15) * 4;

    float mv[NSPLIT], lv[NSPLIT];
    float M = -1e30f;
    #pragma unroll
    for (int s = 0; s < NSPLIT; s++) {
        mv[s] = g_m[s][row];
        lv[s] = g_l[s][row];
        M = fmaxf(M, mv[s]);
    }
    float w[NSPLIT], denom = 0.f;
    #pragma unroll
    for (int s = 0; s < NSPLIT; s++) {
        w[s] = __expf(mv[s] - M);
        denom += w[s] * lv[s];
    }
    float inv = 1.0f / denom;

    float4 r = make_float4(0.f, 0.f, 0.f, 0.f);
    #pragma unroll
    for (int s = 0; s < NSPLIT; s++) {
        float4 o = *(const float4*)&g_opart[s][(size_t)row * H + c4];
        r.x += w[s] * o.x; r.y += w[s] * o.y; r.z += w[s] * o.z; r.w += w[s] * o.w;
    }
    r.x *= inv; r.y *= inv; r.z *= inv; r.w *= inv;
    *(float4*)&out[(size_t)row * H + c4] = r;
}

// ===========================================================================
extern "C" void kernel_launch(void* const* d_in, const int* in_sizes, int n_in,
                              void* d_out, int out_size)
{
    const float* x  = (const float*)d_in[0];
    const float* Wq = (const float*)d_in[1];
    const float* Wk = (const float*)d_in[2];
    const float* Wv = (const float*)d_in[3];
    float* out = (float*)d_out;

    cudaFuncSetAttribute(proj_mma_kernel,
                         cudaFuncAttributeMaxDynamicSharedMemorySize, PROJ_SMEM);
    cudaFuncSetAttribute(attn_mma_kernel,
                         cudaFuncAttributeMaxDynamicSharedMemorySize, ATTN_SMEM);

    wconv_kernel<<<192, 256>>>(Wq, Wk, Wv);
    proj_mma_kernel<<<dim3(M_TOTAL / 64, 2), 256, PROJ_SMEM>>>(x);
    attn_mma_kernel<<<dim3(T / 64, BATCH, NSPLIT), 256, ATTN_SMEM>>>();
    combine_kernel<<<(M_TOTAL * (H / 4)) / 256, 256>>>(out);
}